// round 8
// baseline (speedup 1.0000x reference)
#include <cuda_runtime.h>

// LDR toeplitz-displacement layer via FFT with 2-term real packing.
//   Hf = fft(D*H); Gf = fft(G); Xf = ifft(conj(D)*x)
//   t = D*fft(Hf.Xf) is REAL => pack two terms: z = u1 + i*u2,
//   W = fft(D.fft(z)) = Tf1 + i*Tf2 (Tf Hermitian), unpack via reversed read.
//   out = Re(ifft(sum Gf.Tf)) / (2N).
// K1 prep (256 blk, NT=256, 2 CTA/SM): radix-16 Stockham -> g_Hf, g_Gf, g_Xf.
// K2 main (128 blk, NT=256): per (j,b), 8 chains processed as 4 PAIRS with
//   two independent FFT pipelines sharing each __syncthreads (latency hiding),
//   in-place digit-swapped DFT16, acc in smem, final radix-16 IFFT.

#define NN    4096
#define CIN   4
#define COUT  4
#define RANK  4
#define BATCH 32

#define NT    256
#define PIDX16(i) ((i) + ((i) >> 4))
#define NPAD16 4352
#define W16SIZE 256

#define PREP_SMEM ((2 * NPAD16 + W16SIZE) * (int)sizeof(float2))
// main: a0 a1 b0 b1 (NPAD16 each) + acc[NN] + W[256]
#define MAIN_SMEM ((4 * NPAD16 + NN + W16SIZE) * (int)sizeof(float2))

__device__ float2 g_Hf[CIN*COUT*RANK][NN];   // 2 MB
__device__ float2 g_Gf[CIN*COUT*RANK][NN];   // 2 MB
__device__ float2 g_Xf[CIN*BATCH][NN];       // 4 MB

__device__ __forceinline__ float2 cmul(float2 a, float2 b) {
    return make_float2(a.x*b.x - a.y*b.y, a.x*b.y + a.y*b.x);
}
__device__ __forceinline__ float2 cadd(float2 a, float2 b) { return make_float2(a.x+b.x, a.y+b.y); }
__device__ __forceinline__ float2 csub(float2 a, float2 b) { return make_float2(a.x-b.x, a.y-b.y); }

// ============ radix-16 machinery (in-place digit-swapped DFT16) =============
// swap(m) = ((m&3)<<2) | (m>>2). dft16A: natural in -> X[k] at slot swap(k).
// dft16B: swapped in -> X[k] at slot k. Twiddle slot m by W16^{(m&3)*(m>>2)}.

__device__ __constant__ int SW16[16] = {0,4,8,12, 1,5,9,13, 2,6,10,14, 3,7,11,15};

template<int INV>
__device__ __forceinline__ void dft4ip(float2& a, float2& b, float2& c, float2& d) {
    float2 t0 = cadd(a,c), t1 = csub(a,c), t2 = cadd(b,d), bd = csub(b,d);
    float2 t3 = INV ? make_float2(-bd.y, bd.x) : make_float2(bd.y, -bd.x);
    a = cadd(t0,t2); b = cadd(t1,t3); c = csub(t0,t2); d = csub(t1,t3);
}

template<int INV>
__device__ __forceinline__ void tw16ip(float2 v[16]) {
    const float C1 = 0.92387953251128675613f;
    const float S1 = 0.38268343236508977172f;
    const float CC = 0.70710678118654752440f;
#define TW(m, c, s) v[m] = cmul(v[m], make_float2((c), INV ? (s) : -(s)))
    TW(5,  C1,  S1);
    TW(6,  CC,  CC);
    TW(7,  S1,  C1);
    TW(9,  CC,  CC);
    TW(10, 0.0f, 1.0f);
    TW(11, -CC, CC);
    TW(13, S1,  C1);
    TW(14, -CC, CC);
    TW(15, -C1, -S1);
#undef TW
}

template<int INV>
__device__ __forceinline__ void dft16A(float2 v[16]) {
#pragma unroll
    for (int n0 = 0; n0 < 4; ++n0) dft4ip<INV>(v[n0], v[n0+4], v[n0+8], v[n0+12]);
    tw16ip<INV>(v);
#pragma unroll
    for (int q = 0; q < 4; ++q) dft4ip<INV>(v[4*q], v[4*q+1], v[4*q+2], v[4*q+3]);
}

template<int INV>
__device__ __forceinline__ void dft16B(float2 v[16]) {
#pragma unroll
    for (int q = 0; q < 4; ++q) dft4ip<INV>(v[4*q], v[4*q+1], v[4*q+2], v[4*q+3]);
    tw16ip<INV>(v);
#pragma unroll
    for (int n0 = 0; n0 < 4; ++n0) dft4ip<INV>(v[n0], v[n0+4], v[n0+8], v[n0+12]);
}

template<int INV, int IN_SWAPPED>
__device__ __forceinline__ void stage_store16(float2 v[16], float2* __restrict__ sb,
                                              const float2* __restrict__ W,
                                              int u, int sshift) {
    if (IN_SWAPPED) dft16B<INV>(v); else dft16A<INV>(v);
    const int s  = 1 << sshift;
    const int k1 = u & ~(s - 1);
    const int base = u + 15 * k1;
    float2 w1 = W[k1];
    if (INV) w1.y = -w1.y;
    float2 wp2 = cmul(w1, w1);
    float2 wp3 = cmul(wp2, w1);
    float2 wp4 = cmul(wp2, wp2);
    float2 wp5 = cmul(wp3, wp2);
    float2 wp6 = cmul(wp3, wp3);
    float2 wp7 = cmul(wp4, wp3);
    float2 wp8 = cmul(wp4, wp4);
    float2 wk[16];
    wk[0] = make_float2(1.0f, 0.0f);
    wk[1] = w1;  wk[2] = wp2;  wk[3] = wp3;  wk[4] = wp4;
    wk[5] = wp5; wk[6] = wp6;  wk[7] = wp7;  wk[8] = wp8;
    wk[9]  = cmul(wp8, w1);
    wk[10] = cmul(wp8, wp2);
    wk[11] = cmul(wp8, wp3);
    wk[12] = cmul(wp8, wp4);
    wk[13] = cmul(wp8, wp5);
    wk[14] = cmul(wp8, wp6);
    wk[15] = cmul(wp8, wp7);
#pragma unroll
    for (int k = 0; k < 16; ++k) {
        const float2 o = IN_SWAPPED ? v[k] : v[SW16[k]];
        sb[PIDX16(base + k * s)] = (k == 0) ? o : cmul(o, wk[k]);
    }
}

__device__ __forceinline__ void stage_load16(float2 v[16], const float2* __restrict__ sb, int tid) {
#pragma unroll
    for (int k = 0; k < 16; ++k) v[k] = sb[PIDX16(tid + 256 * k)];
}

// ======================= K1: prep (radix-16, 2 CTA/SM) ======================

__global__ void __launch_bounds__(NT, 2) ldr_prep_kernel(const float* __restrict__ x,
                                                         const float* __restrict__ G,
                                                         const float* __restrict__ H)
{
    extern __shared__ float2 smem2[];
    float2* b0 = smem2;
    float2* b1 = smem2 + NPAD16;
    float2* W  = smem2 + 2 * NPAD16;
    const int tid = threadIdx.x;
    {
        float s, c; sincospif((float)tid * (1.0f / 2048.0f), &s, &c);
        W[tid] = make_float2(c, -s);
    }

    const int bid = blockIdx.x;
    float2 v[16];
    float2* dstrow;
    int inv_mode = 0;
    if (bid < 64) {                       // Hf = fft(D * H)
        const float* h = H + bid * NN;
#pragma unroll
        for (int k = 0; k < 16; ++k) {
            const int n = tid + 256 * k;
            float s, c; sincospif((float)n * (1.0f / 4096.0f), &s, &c);
            const float val = h[n];
            v[k] = make_float2(val * c, val * s);
        }
        dstrow = g_Hf[bid];
    } else if (bid < 128) {               // Gf = fft(G)
        const float* g = G + (bid - 64) * NN;
#pragma unroll
        for (int k = 0; k < 16; ++k) v[k] = make_float2(g[tid + 256 * k], 0.0f);
        dstrow = g_Gf[bid - 64];
    } else {                              // Xf = ifft(conj(D) * x) (with 1/N)
        const float* xp = x + (bid - 128) * NN;
#pragma unroll
        for (int k = 0; k < 16; ++k) {
            const int n = tid + 256 * k;
            float s, c; sincospif((float)n * (1.0f / 4096.0f), &s, &c);
            const float val = xp[n];
            v[k] = make_float2(val * c, -val * s);
        }
        dstrow = g_Xf[bid - 128];
        inv_mode = 1;
    }
    __syncthreads();   // W visible

    if (!inv_mode) {
        stage_store16<0,0>(v, b0, W, tid, 0);
        __syncthreads();
        stage_load16(v, b0, tid);
        stage_store16<0,0>(v, b1, W, tid, 4);
        __syncthreads();
        stage_load16(v, b1, tid);
        dft16A<0>(v);     // swapped
#pragma unroll
        for (int k = 0; k < 16; ++k) dstrow[tid + 256 * k] = v[SW16[k]];
    } else {
        stage_store16<1,0>(v, b0, W, tid, 0);
        __syncthreads();
        stage_load16(v, b0, tid);
        stage_store16<1,0>(v, b1, W, tid, 4);
        __syncthreads();
        stage_load16(v, b1, tid);
        dft16A<1>(v);     // swapped
        const float inv = 1.0f / (float)NN;
#pragma unroll
        for (int k = 0; k < 16; ++k) {
            const float2 o = v[SW16[k]];
            dstrow[tid + 256 * k] = make_float2(o.x * inv, o.y * inv);
        }
    }
}

// ============== K2: main — paired chains with shared barriers ===============

// e^{i*pi*k/16}
__device__ __constant__ float E16C[16] = { 1.0f, 0.98078528040323044913f,
    0.92387953251128675613f, 0.83146961230254523708f, 0.70710678118654752440f,
    0.55557023301960222474f, 0.38268343236508977172f, 0.19509032201612826785f,
    0.0f, -0.19509032201612826785f, -0.38268343236508977172f,
    -0.55557023301960222474f, -0.70710678118654752440f, -0.83146961230254523708f,
    -0.92387953251128675613f, -0.98078528040323044913f };
__device__ __constant__ float E16S[16] = { 0.0f, 0.19509032201612826785f,
    0.38268343236508977172f, 0.55557023301960222474f, 0.70710678118654752440f,
    0.83146961230254523708f, 0.92387953251128675613f, 0.98078528040323044913f,
    1.0f, 0.98078528040323044913f, 0.92387953251128675613f,
    0.83146961230254523708f, 0.70710678118654752440f, 0.55557023301960222474f,
    0.38268343236508977172f, 0.19509032201612826785f };

// One PAIR of chains (A,B). Buffers A0/A1 for A, B0/B1 for B; 5 joint barriers.
__device__ __forceinline__ void do_pair(const float2* __restrict__ hfA1,
                                        const float2* __restrict__ hfA2,
                                        const float2* __restrict__ gfA1,
                                        const float2* __restrict__ gfA2,
                                        const float2* __restrict__ xfA,
                                        const float2* __restrict__ hfB1,
                                        const float2* __restrict__ hfB2,
                                        const float2* __restrict__ gfB1,
                                        const float2* __restrict__ gfB2,
                                        const float2* __restrict__ xfB,
                                        float2* A0, float2* A1,
                                        float2* B0, float2* B1,
                                        float2* __restrict__ accs,
                                        const float2* __restrict__ W,
                                        float2 d0, int tid)
{
    float2 vA[16], vB[16];
    // pack z = u1 + i*u2
#pragma unroll
    for (int k = 0; k < 16; ++k) {
        const int n = tid + 256 * k;
        const float2 xvA = xfA[n];
        const float2 u1 = cmul(hfA1[n], xvA);
        const float2 u2 = cmul(hfA2[n], xvA);
        vA[k] = make_float2(u1.x - u2.y, u1.y + u2.x);
    }
#pragma unroll
    for (int k = 0; k < 16; ++k) {
        const int n = tid + 256 * k;
        const float2 xvB = xfB[n];
        const float2 u1 = cmul(hfB1[n], xvB);
        const float2 u2 = cmul(hfB2[n], xvB);
        vB[k] = make_float2(u1.x - u2.y, u1.y + u2.x);
    }
    // fft #1
    stage_store16<0,0>(vA, A0, W, tid, 0);
    stage_store16<0,0>(vB, B0, W, tid, 0);
    __syncthreads();                                   // bar1
    stage_load16(vA, A0, tid);
    stage_store16<0,0>(vA, A1, W, tid, 4);
    stage_load16(vB, B0, tid);
    stage_store16<0,0>(vB, B1, W, tid, 4);
    __syncthreads();                                   // bar2
    stage_load16(vA, A1, tid);
    dft16A<0>(vA);                                     // swapped
    stage_load16(vB, B1, tid);
    dft16A<0>(vB);                                     // swapped
    // D multiply in swapped slots: slot m holds n = tid + 256*SW16[m]
#pragma unroll
    for (int m = 0; m < 16; ++m) {
        const float2 e = cmul(d0, make_float2(E16C[SW16[m]], E16S[SW16[m]]));
        vA[m] = cmul(vA[m], e);
        vB[m] = cmul(vB[m], e);
    }
    // fft #2 (input swapped)
    stage_store16<0,1>(vA, A0, W, tid, 0);
    stage_store16<0,1>(vB, B0, W, tid, 0);
    __syncthreads();                                   // bar3
    stage_load16(vA, A0, tid);
    stage_store16<0,0>(vA, A1, W, tid, 4);
    stage_load16(vB, B0, tid);
    stage_store16<0,0>(vB, B1, W, tid, 4);
    __syncthreads();                                   // bar4
    stage_load16(vA, A1, tid);
    dft16A<0>(vA);                                     // swapped
    stage_load16(vB, B1, tid);
    dft16A<0>(vB);                                     // swapped
    // Hermitian unpack stores (natural order)
#pragma unroll
    for (int k = 0; k < 16; ++k) A0[PIDX16(tid + 256 * k)] = vA[SW16[k]];
#pragma unroll
    for (int k = 0; k < 16; ++k) B0[PIDX16(tid + 256 * k)] = vB[SW16[k]];
    __syncthreads();                                   // bar5
#pragma unroll
    for (int k = 0; k < 16; ++k) {
        const int n   = tid + 256 * k;
        const int rev = (NN - n) & (NN - 1);
        const float2 wsA = A0[PIDX16(rev)];
        const float2 vkA = vA[SW16[k]];
        const float2 t1A = make_float2(vkA.x + wsA.x, vkA.y - wsA.y);   // 2*Tf1
        const float2 t2A = make_float2(vkA.y + wsA.y, wsA.x - vkA.x);   // 2*Tf2
        float2 contrib = cadd(cmul(gfA1[n], t1A), cmul(gfA2[n], t2A));
        const float2 wsB = B0[PIDX16(rev)];
        const float2 vkB = vB[SW16[k]];
        const float2 t1B = make_float2(vkB.x + wsB.x, vkB.y - wsB.y);
        const float2 t2B = make_float2(vkB.y + wsB.y, wsB.x - vkB.x);
        contrib = cadd(contrib, cadd(cmul(gfB1[n], t1B), cmul(gfB2[n], t2B)));
        accs[n] = cadd(accs[n], contrib);              // thread-exclusive
    }
}

__global__ void __launch_bounds__(NT, 1) ldr_main_kernel(float* __restrict__ out)
{
    extern __shared__ float2 smem2[];
    float2* a0   = smem2;
    float2* a1   = smem2 + NPAD16;
    float2* b0   = smem2 + 2 * NPAD16;
    float2* b1   = smem2 + 3 * NPAD16;
    float2* accs = smem2 + 4 * NPAD16;         // [NN], unpadded (thread-exclusive)
    float2* W    = smem2 + 4 * NPAD16 + NN;
    const int tid = threadIdx.x;
    {
        float s, c; sincospif((float)tid * (1.0f / 2048.0f), &s, &c);
        W[tid] = make_float2(c, -s);
    }
    float2 d0;
    { float s, c; sincospif((float)tid * (1.0f / 4096.0f), &s, &c); d0 = make_float2(c, s); }
#pragma unroll
    for (int k = 0; k < 16; ++k) accs[tid + 256 * k] = make_float2(0.0f, 0.0f);

    const int j = blockIdx.x >> 5;
    const int b = blockIdx.x & 31;
    __syncthreads();   // W visible

    // 8 chains as 4 pairs; pair p: chains (2p, 2p+1); chain c: i=c>>1, sp=c&1.
    // Buffer parity alternates per pair (A-first-store: p even -> a0, odd -> a1).
#pragma unroll 1
    for (int p = 0; p < 4; ++p) {
        const int cA = 2 * p,      iA = cA >> 1, spA = cA & 1;
        const int cB = 2 * p + 1,  iB = cB >> 1, spB = cB & 1;
        const int rA = (iA * COUT + j) * RANK + 2 * spA;
        const int rB = (iB * COUT + j) * RANK + 2 * spB;
        if ((p & 1) == 0) {
            do_pair(g_Hf[rA], g_Hf[rA+1], g_Gf[rA], g_Gf[rA+1], g_Xf[iA*BATCH + b],
                    g_Hf[rB], g_Hf[rB+1], g_Gf[rB], g_Gf[rB+1], g_Xf[iB*BATCH + b],
                    a0, a1, b0, b1, accs, W, d0, tid);
        } else {
            do_pair(g_Hf[rA], g_Hf[rA+1], g_Gf[rA], g_Gf[rA+1], g_Xf[iA*BATCH + b],
                    g_Hf[rB], g_Hf[rB+1], g_Gf[rB], g_Gf[rB+1], g_Xf[iB*BATCH + b],
                    a1, a0, b1, b0, accs, W, d0, tid);
        }
    }

    // final IFFT of acc (pair 3 had parity 1: its unpack wrote/read a1,b1;
    // a0's last readers are >=2 barriers back -> safe to store first).
    float2 v[16];
#pragma unroll
    for (int k = 0; k < 16; ++k) v[k] = accs[tid + 256 * k];
    stage_store16<1,0>(v, a0, W, tid, 0);
    __syncthreads();
    stage_load16(v, a0, tid);
    stage_store16<1,0>(v, a1, W, tid, 4);
    __syncthreads();
    stage_load16(v, a1, tid);
    dft16A<1>(v);                                      // swapped
    float* op = out + (j * BATCH + b) * NN;
    const float inv = 1.0f / (2.0f * (float)NN);
#pragma unroll
    for (int k = 0; k < 16; ++k) op[tid + 256 * k] = v[SW16[k]].x * inv;
}

extern "C" void kernel_launch(void* const* d_in, const int* in_sizes, int n_in,
                              void* d_out, int out_size)
{
    const float* x = (const float*)d_in[0];   // (4, 32, 4096)
    const float* G = (const float*)d_in[1];   // (4, 4, 4, 4096)
    const float* H = (const float*)d_in[2];   // (4, 4, 4, 4096)
    float* out = (float*)d_out;               // (4, 32, 4096)

    cudaFuncSetAttribute(ldr_prep_kernel, cudaFuncAttributeMaxDynamicSharedMemorySize, PREP_SMEM);
    cudaFuncSetAttribute(ldr_main_kernel, cudaFuncAttributeMaxDynamicSharedMemorySize, MAIN_SMEM);

    ldr_prep_kernel<<<256, NT, PREP_SMEM>>>(x, G, H);
    ldr_main_kernel<<<128, NT, MAIN_SMEM>>>(out);
}

// round 10
// speedup vs baseline: 6.4903x; 6.4903x over previous
#include <cuda_runtime.h>

// LDR toeplitz-displacement layer via FFT with 2-term real packing everywhere.
//   Hf = fft(D*H); Gf = fft(G); Xf = ifft(conj(D)*x)
//   t = D*fft(Hf.Xf) is REAL => pack two chain terms: z = u1 + i*u2,
//   W = fft(D.fft(z)) = Tf1 + i*Tf2 (Tf Hermitian), unpack via reversed read.
//   out = Re(ifft(sum Gf.Tf)) / (2N).
// Prep also packs PAIRS of real rows per FFT:
//   conj(Hf[k]) = Hf[(1-k) mod N], conj(Xf[k]) = Xf[(1-k) mod N] (shifted
//   Hermitian), conj(Gf[k]) = Gf[(N-k) mod N] => unpack a+ib with sigma-read.
// FFT: radix-16 Stockham, NT=256, 2 smem exchanges, in-place digit-swapped
// DFT16 (swap(m) = ((m&3)<<2)|(m>>2), compile-time).

#define NN    4096
#define CIN   4
#define COUT  4
#define RANK  4
#define BATCH 32

#define NT    256
#define PIDX16(i) ((i) + ((i) >> 4))
#define NPAD16 4352
#define W16SIZE 256
#define LDR_SMEM ((2 * NPAD16 + W16SIZE) * (int)sizeof(float2))

#define SW16(m) ((((m) & 3) << 2) | ((m) >> 2))

__device__ float2 g_Hf[CIN*COUT*RANK][NN];   // 2 MB
__device__ float2 g_Gf[CIN*COUT*RANK][NN];   // 2 MB
__device__ float2 g_Xf[CIN*BATCH][NN];       // 4 MB

__device__ __forceinline__ float2 cmul(float2 a, float2 b) {
    return make_float2(a.x*b.x - a.y*b.y, a.x*b.y + a.y*b.x);
}
__device__ __forceinline__ float2 cadd(float2 a, float2 b) { return make_float2(a.x+b.x, a.y+b.y); }
__device__ __forceinline__ float2 csub(float2 a, float2 b) { return make_float2(a.x-b.x, a.y-b.y); }

// ============ radix-16 machinery (in-place digit-swapped DFT16) =============
// dft16A: natural in -> X[k] at slot SW16(k). dft16B: swapped in -> X[k] at k.

template<int INV>
__device__ __forceinline__ void dft4ip(float2& a, float2& b, float2& c, float2& d) {
    float2 t0 = cadd(a,c), t1 = csub(a,c), t2 = cadd(b,d), bd = csub(b,d);
    float2 t3 = INV ? make_float2(-bd.y, bd.x) : make_float2(bd.y, -bd.x);
    a = cadd(t0,t2); b = cadd(t1,t3); c = csub(t0,t2); d = csub(t1,t3);
}

template<int INV>
__device__ __forceinline__ void tw16ip(float2 v[16]) {
    const float C1 = 0.92387953251128675613f;
    const float S1 = 0.38268343236508977172f;
    const float CC = 0.70710678118654752440f;
#define TW(m, c, s) v[m] = cmul(v[m], make_float2((c), INV ? (s) : -(s)))
    TW(5,  C1,  S1);
    TW(6,  CC,  CC);
    TW(7,  S1,  C1);
    TW(9,  CC,  CC);
    TW(10, 0.0f, 1.0f);
    TW(11, -CC, CC);
    TW(13, S1,  C1);
    TW(14, -CC, CC);
    TW(15, -C1, -S1);
#undef TW
}

template<int INV>
__device__ __forceinline__ void dft16A(float2 v[16]) {
#pragma unroll
    for (int n0 = 0; n0 < 4; ++n0) dft4ip<INV>(v[n0], v[n0+4], v[n0+8], v[n0+12]);
    tw16ip<INV>(v);
#pragma unroll
    for (int q = 0; q < 4; ++q) dft4ip<INV>(v[4*q], v[4*q+1], v[4*q+2], v[4*q+3]);
}

template<int INV>
__device__ __forceinline__ void dft16B(float2 v[16]) {
#pragma unroll
    for (int q = 0; q < 4; ++q) dft4ip<INV>(v[4*q], v[4*q+1], v[4*q+2], v[4*q+3]);
    tw16ip<INV>(v);
#pragma unroll
    for (int n0 = 0; n0 < 4; ++n0) dft4ip<INV>(v[n0], v[n0+4], v[n0+8], v[n0+12]);
}

template<int INV, int IN_SWAPPED>
__device__ __forceinline__ void stage_store16(float2 v[16], float2* __restrict__ sb,
                                              const float2* __restrict__ W,
                                              int u, int sshift) {
    if (IN_SWAPPED) dft16B<INV>(v); else dft16A<INV>(v);
    const int s  = 1 << sshift;
    const int k1 = u & ~(s - 1);
    const int base = u + 15 * k1;
    float2 w1 = W[k1];
    if (INV) w1.y = -w1.y;
    float2 wp2 = cmul(w1, w1);
    float2 wp3 = cmul(wp2, w1);
    float2 wp4 = cmul(wp2, wp2);
    float2 wp5 = cmul(wp3, wp2);
    float2 wp6 = cmul(wp3, wp3);
    float2 wp7 = cmul(wp4, wp3);
    float2 wp8 = cmul(wp4, wp4);
    float2 wk[16];
    wk[0] = make_float2(1.0f, 0.0f);
    wk[1] = w1;  wk[2] = wp2;  wk[3] = wp3;  wk[4] = wp4;
    wk[5] = wp5; wk[6] = wp6;  wk[7] = wp7;  wk[8] = wp8;
    wk[9]  = cmul(wp8, w1);
    wk[10] = cmul(wp8, wp2);
    wk[11] = cmul(wp8, wp3);
    wk[12] = cmul(wp8, wp4);
    wk[13] = cmul(wp8, wp5);
    wk[14] = cmul(wp8, wp6);
    wk[15] = cmul(wp8, wp7);
#pragma unroll
    for (int k = 0; k < 16; ++k) {
        const float2 o = IN_SWAPPED ? v[k] : v[SW16(k)];
        sb[PIDX16(base + k * s)] = (k == 0) ? o : cmul(o, wk[k]);
    }
}

__device__ __forceinline__ void stage_load16(float2 v[16], const float2* __restrict__ sb, int tid) {
#pragma unroll
    for (int k = 0; k < 16; ++k) v[k] = sb[PIDX16(tid + 256 * k)];
}

// ================ K1: prep, 2 real rows packed per FFT ======================
// bid<32: Hf pair; 32<=bid<64: Gf pair; 64<=bid<128: Xf pair.

__global__ void __launch_bounds__(NT, 2) ldr_prep_kernel(const float* __restrict__ x,
                                                         const float* __restrict__ G,
                                                         const float* __restrict__ H)
{
    extern __shared__ float2 smem2[];
    float2* b0 = smem2;
    float2* b1 = smem2 + NPAD16;
    float2* W  = smem2 + 2 * NPAD16;
    const int tid = threadIdx.x;
    {
        float s, c; sincospif((float)tid * (1.0f / 2048.0f), &s, &c);
        W[tid] = make_float2(c, -s);
    }

    const int bid = blockIdx.x;
    float2 v[16];
    float2 *dst1, *dst2;
    int inv_mode = 0;        // 0: forward fft; 1: inverse fft
    int shift_rev = 1;       // sigma(n) = (shift_rev - n) mod N  (1 or 0->N-n)
    float scale = 0.5f;

    if (bid < 32) {          // Hf rows 2bid, 2bid+1: fft(D * h)
        const float* h1 = H + (2 * bid) * NN;
        const float* h2 = H + (2 * bid + 1) * NN;
#pragma unroll
        for (int k = 0; k < 16; ++k) {
            const int n = tid + 256 * k;
            float s, c; sincospif((float)n * (1.0f / 4096.0f), &s, &c);
            v[k] = cmul(make_float2(c, s), make_float2(h1[n], h2[n]));
        }
        dst1 = g_Hf[2 * bid]; dst2 = g_Hf[2 * bid + 1];
    } else if (bid < 64) {   // Gf rows: fft(g)
        const int r = bid - 32;
        const float* g1 = G + (2 * r) * NN;
        const float* g2 = G + (2 * r + 1) * NN;
#pragma unroll
        for (int k = 0; k < 16; ++k) {
            const int n = tid + 256 * k;
            v[k] = make_float2(g1[n], g2[n]);
        }
        dst1 = g_Gf[2 * r]; dst2 = g_Gf[2 * r + 1];
        shift_rev = 0;       // plain Hermitian: sigma(n) = (N - n) mod N
    } else {                 // Xf rows: ifft(conj(D) * x) with 1/N
        const int r = bid - 64;
        const float* x1 = x + (2 * r) * NN;
        const float* x2 = x + (2 * r + 1) * NN;
#pragma unroll
        for (int k = 0; k < 16; ++k) {
            const int n = tid + 256 * k;
            float s, c; sincospif((float)n * (1.0f / 4096.0f), &s, &c);
            v[k] = cmul(make_float2(c, -s), make_float2(x1[n], x2[n]));
        }
        dst1 = g_Xf[2 * r]; dst2 = g_Xf[2 * r + 1];
        inv_mode = 1;
        scale = 0.5f / (float)NN;
    }
    __syncthreads();   // W visible

    if (!inv_mode) {
        stage_store16<0,0>(v, b0, W, tid, 0);
        __syncthreads();
        stage_load16(v, b0, tid);
        stage_store16<0,0>(v, b1, W, tid, 4);
        __syncthreads();
        stage_load16(v, b1, tid);
        dft16A<0>(v);                      // swapped
    } else {
        stage_store16<1,0>(v, b0, W, tid, 0);
        __syncthreads();
        stage_load16(v, b0, tid);
        stage_store16<1,0>(v, b1, W, tid, 4);
        __syncthreads();
        stage_load16(v, b1, tid);
        dft16A<1>(v);                      // swapped
    }

    // unpack exchange: natural-order Z into b0 (b0's last readers pre-barrier)
#pragma unroll
    for (int k = 0; k < 16; ++k) b0[PIDX16(tid + 256 * k)] = v[SW16(k)];
    __syncthreads();
#pragma unroll
    for (int k = 0; k < 16; ++k) {
        const int n   = tid + 256 * k;
        const int sg  = (shift_rev - n) & (NN - 1);
        const float2 z  = v[SW16(k)];
        const float2 ws = b0[PIDX16(sg)];
        // A = (z + conj(ws))/2 ; B = -i(z - conj(ws))/2   (scale applied)
        dst1[n] = make_float2(scale * (z.x + ws.x), scale * (z.y - ws.y));
        dst2[n] = make_float2(scale * (z.y + ws.y), scale * (ws.x - z.x));
    }
}

// ===================== K2: main (one (j,b) per block) =======================

// e^{i*pi*k/16}
__device__ __constant__ float E16C[16] = { 1.0f, 0.98078528040323044913f,
    0.92387953251128675613f, 0.83146961230254523708f, 0.70710678118654752440f,
    0.55557023301960222474f, 0.38268343236508977172f, 0.19509032201612826785f,
    0.0f, -0.19509032201612826785f, -0.38268343236508977172f,
    -0.55557023301960222474f, -0.70710678118654752440f, -0.83146961230254523708f,
    -0.92387953251128675613f, -0.98078528040323044913f };
__device__ __constant__ float E16S[16] = { 0.0f, 0.19509032201612826785f,
    0.38268343236508977172f, 0.55557023301960222474f, 0.70710678118654752440f,
    0.83146961230254523708f, 0.92387953251128675613f, 0.98078528040323044913f,
    1.0f, 0.98078528040323044913f, 0.92387953251128675613f,
    0.83146961230254523708f, 0.70710678118654752440f, 0.55557023301960222474f,
    0.38268343236508977172f, 0.19509032201612826785f };

// one packed chain; A is stored 3x (s1 of both ffts + unpack), B 2x (s16).
__device__ __forceinline__ void do_chain(const float2* __restrict__ hf1,
                                         const float2* __restrict__ hf2,
                                         const float2* __restrict__ gf1,
                                         const float2* __restrict__ gf2,
                                         const float2* __restrict__ xf,
                                         float2* A, float2* B,
                                         const float2* __restrict__ W,
                                         float2 d0, float2 acc[16], int tid)
{
    float2 v[16];
#pragma unroll
    for (int k = 0; k < 16; ++k) {
        const int n = tid + 256 * k;
        const float2 xv = xf[n];
        const float2 u1 = cmul(hf1[n], xv);
        const float2 u2 = cmul(hf2[n], xv);
        v[k] = make_float2(u1.x - u2.y, u1.y + u2.x);   // u1 + i*u2
    }
    // fft #1
    stage_store16<0,0>(v, A, W, tid, 0);
    __syncthreads();
    stage_load16(v, A, tid);
    stage_store16<0,0>(v, B, W, tid, 4);
    __syncthreads();
    stage_load16(v, B, tid);
    dft16A<0>(v);                                      // swapped
    // D multiply in swapped slots: slot m holds n = tid + 256*SW16(m)
#pragma unroll
    for (int m = 0; m < 16; ++m)
        v[m] = cmul(v[m], cmul(d0, make_float2(E16C[SW16(m)], E16S[SW16(m)])));
    // fft #2 (input swapped)
    stage_store16<0,1>(v, A, W, tid, 0);
    __syncthreads();
    stage_load16(v, A, tid);
    stage_store16<0,0>(v, B, W, tid, 4);
    __syncthreads();
    stage_load16(v, B, tid);
    dft16A<0>(v);                                      // swapped
    // Hermitian unpack through A
#pragma unroll
    for (int k = 0; k < 16; ++k) A[PIDX16(tid + 256 * k)] = v[SW16(k)];
    __syncthreads();
#pragma unroll
    for (int k = 0; k < 16; ++k) {
        const int n   = tid + 256 * k;
        const int rev = (NN - n) & (NN - 1);
        const float2 ws = A[PIDX16(rev)];
        const float2 vk = v[SW16(k)];
        const float2 t1 = make_float2(vk.x + ws.x, vk.y - ws.y);   // 2*Tf1
        const float2 t2 = make_float2(vk.y + ws.y, ws.x - vk.x);   // 2*Tf2
        acc[k] = cadd(acc[k], cadd(cmul(gf1[n], t1), cmul(gf2[n], t2)));
    }
}

__global__ void __launch_bounds__(NT, 1) ldr_main_kernel(float* __restrict__ out)
{
    extern __shared__ float2 smem2[];
    float2* b0 = smem2;
    float2* b1 = smem2 + NPAD16;
    float2* W  = smem2 + 2 * NPAD16;
    const int tid = threadIdx.x;
    {
        float s, c; sincospif((float)tid * (1.0f / 2048.0f), &s, &c);
        W[tid] = make_float2(c, -s);
    }
    float2 d0;
    { float s, c; sincospif((float)tid * (1.0f / 4096.0f), &s, &c); d0 = make_float2(c, s); }
    __syncthreads();   // W visible

    const int j = blockIdx.x >> 5;
    const int b = blockIdx.x & 31;

    float2 acc[16];
#pragma unroll
    for (int k = 0; k < 16; ++k) acc[k] = make_float2(0.0f, 0.0f);

    // 8 chains: chain c -> i = c>>1, sp = c&1, rows r1, r1+1.
    // Buffer parity alternates per chain: even (A=b0,B=b1), odd (A=b1,B=b0).
#pragma unroll 1
    for (int c = 0; c < 8; c += 2) {
        {
            const int i  = (c    ) >> 1, sp = (c    ) & 1;
            const int r1 = (i * COUT + j) * RANK + 2 * sp;
            do_chain(g_Hf[r1], g_Hf[r1+1], g_Gf[r1], g_Gf[r1+1],
                     g_Xf[i * BATCH + b], b0, b1, W, d0, acc, tid);
        }
        {
            const int i  = (c + 1) >> 1, sp = (c + 1) & 1;
            const int r1 = (i * COUT + j) * RANK + 2 * sp;
            do_chain(g_Hf[r1], g_Hf[r1+1], g_Gf[r1], g_Gf[r1+1],
                     g_Xf[i * BATCH + b], b1, b0, W, d0, acc, tid);
        }
    }

    // final IFFT of acc. Chain 7 (A=b1): b0's last reads pre-unpack-barrier,
    // so storing b0 first is one-barrier separated.
    stage_store16<1,0>(acc, b0, W, tid, 0);
    __syncthreads();
    stage_load16(acc, b0, tid);
    stage_store16<1,0>(acc, b1, W, tid, 4);
    __syncthreads();
    stage_load16(acc, b1, tid);
    dft16A<1>(acc);                                    // swapped
    float* op = out + (j * BATCH + b) * NN;
    const float inv = 1.0f / (2.0f * (float)NN);
#pragma unroll
    for (int k = 0; k < 16; ++k) op[tid + 256 * k] = acc[SW16(k)].x * inv;
}

extern "C" void kernel_launch(void* const* d_in, const int* in_sizes, int n_in,
                              void* d_out, int out_size)
{
    const float* x = (const float*)d_in[0];   // (4, 32, 4096)
    const float* G = (const float*)d_in[1];   // (4, 4, 4, 4096)
    const float* H = (const float*)d_in[2];   // (4, 4, 4, 4096)
    float* out = (float*)d_out;               // (4, 32, 4096)

    cudaFuncSetAttribute(ldr_prep_kernel, cudaFuncAttributeMaxDynamicSharedMemorySize, LDR_SMEM);
    cudaFuncSetAttribute(ldr_main_kernel, cudaFuncAttributeMaxDynamicSharedMemorySize, LDR_SMEM);

    ldr_prep_kernel<<<128, NT, LDR_SMEM>>>(x, G, H);
    ldr_main_kernel<<<128, NT, LDR_SMEM>>>(out);
}